// round 13
// baseline (speedup 1.0000x reference)
#include <cuda_runtime.h>

typedef unsigned long long u64;
typedef unsigned int u32;

// ---- packed f32x2 helpers (Blackwell FFMA2 path) ----
__device__ __forceinline__ void fma2(u64 &d, u64 a, u64 b) {
    asm volatile("fma.rn.f32x2 %0, %1, %2, %0;" : "+l"(d) : "l"(a), "l"(b));
}
__device__ __forceinline__ u64 dup2(float x) {
    u64 r; asm("mov.b64 %0, {%1, %1};" : "=l"(r) : "f"(x)); return r;
}
__device__ __forceinline__ float2 unpk(u64 v) {
    float lo, hi; asm("mov.b64 {%0, %1}, %2;" : "=f"(lo), "=f"(hi) : "l"(v));
    return make_float2(lo, hi);
}
__device__ __forceinline__ void cp16(u32 dst, const float* src) {
    asm volatile("cp.async.cg.shared.global [%0], [%1], 16;" :: "r"(dst), "l"(src));
}
__device__ __forceinline__ void cp_commit() { asm volatile("cp.async.commit_group;"); }
__device__ __forceinline__ void cp_wait0()  { asm volatile("cp.async.wait_group 0;"); }

#define VSEL(v,u) ((u)==0?(v).x:(u)==1?(v).y:(u)==2?(v).z:(v).w)

// q:(4,16,1024,64) k:(4,16,64,1024) v:(4,16,1024,64)
// prev:(4,16,1024,1024) mask:(1,16,1024,1024) scale:(1)
// out tuple: output ++ weights ++ scores

#define WS 132   // w_s row stride

// smem floats:
//  [0,2048)        q_s (pass A q^T)
//  [2048,18432)    kv_s: K [64][256] (pass A) | stage bufs 2x8192 (pass B) | scratch @combine
//  [18432,22656)   w_s [32][132] (pass B)
//  [22656,22720)   rsum_p[64]    [22720,22752) rinv[32]
#define SMEM_FLOATS 22752
#define SMEM_BYTES  (SMEM_FLOATS * 4)

__global__ void __launch_bounds__(256, 2)
attn_fused5_kernel(const float* __restrict__ q, const float* __restrict__ k,
                   const float* __restrict__ v, const float* __restrict__ prev,
                   const float* __restrict__ mask, const float* __restrict__ scale_p,
                   float* __restrict__ out, float* __restrict__ wts, float* __restrict__ scr)
{
    extern __shared__ float sm[];
    float* q_s     = sm;                // 2048
    float* kv_s    = sm + 2048;         // 16384
    float* w_s     = sm + 18432;        // 4224
    float* stage   = kv_s;              // pass B: 2 x (scores 4096 + mask 4096)
    float* scratch = kv_s;              // combine scratch: 3*2176 = 6528
    float* rsum_p  = sm + 22656;        // [64]
    float* rinv    = sm + 22720;        // [32]

    const int tid = threadIdx.x;
    const int bid = blockIdx.x;
    const int qt  = bid & 31;
    const int bh  = bid >> 5;
    const int h   = bh & 15;

    const float scale = scale_p[0];

    const float* qp = q    + ((size_t)bh * 1024 + (size_t)qt * 32) * 64;
    const float* kp = k    + (size_t)bh * 65536;
    const float* vp = v    + (size_t)bh * 65536;
    const float* pp = prev + ((size_t)bh * 1024 + (size_t)qt * 32) * 1024;
    const float* mp = mask + ((size_t)h  * 1024 + (size_t)qt * 32) * 1024;
    float* op = out + ((size_t)bh * 1024 + (size_t)qt * 32) * 64;
    float* wp = wts + ((size_t)bh * 1024 + (size_t)qt * 32) * 1024;
    float* sp = scr + ((size_t)bh * 1024 + (size_t)qt * 32) * 1024;

    const u32 kv_sh = (u32)__cvta_generic_to_shared(kv_s);

    // ---- stage K chunk 0 ----
    #pragma unroll
    for (int j = 0; j < 16; j++) {
        int idx = j * 1024 + tid * 4;
        int d = idx >> 8, s = idx & 255;
        cp16(kv_sh + idx * 4, kp + d * 1024 + s);
    }
    cp_commit();

    // ---- Q tile (32x64) transposed into q_s[d*32 + r] ----
    #pragma unroll
    for (int i = 0; i < 2; i++) {
        int idx = i * 1024 + tid * 4;
        float4 val = *(const float4*)(qp + idx);
        int r = idx >> 6, d0 = idx & 63;
        q_s[(d0 + 0) * 32 + r] = val.x;
        q_s[(d0 + 1) * 32 + r] = val.y;
        q_s[(d0 + 2) * 32 + r] = val.z;
        q_s[(d0 + 3) * 32 + r] = val.w;
    }

    const int w  = tid >> 5;
    const int tx = tid & 31;

    // =============== Pass A: scores = qk*scale + prev ; exp + rowsum fused ===============
    // 8 warps = 4 rowgroups (8 rows) x 2 sgroups; lane tile = 8 rows x 4 CONSECUTIVE s
    const int rg = w >> 1, sgA = w & 1;
    const int r0 = rg * 8;
    const int sbase = sgA * 128 + tx * 4;   // local s in [0,256), 4 consecutive

    float lsum[8];
    #pragma unroll
    for (int i = 0; i < 8; i++) lsum[i] = 0.f;

    for (int c = 0; c < 4; c++) {
        // prefetch prev for this chunk into registers (lands under the mainloop)
        float4 pf[8];
        #pragma unroll
        for (int i = 0; i < 8; i++)
            pf[i] = *(const float4*)(pp + (r0 + i) * 1024 + c * 256 + sbase);

        cp_wait0();
        __syncthreads();             // K chunk c staged

        u64 acc[8][2];
        #pragma unroll
        for (int i = 0; i < 8; i++) { acc[i][0] = 0ull; acc[i][1] = 0ull; }

        #pragma unroll 8
        for (int d = 0; d < 64; d++) {
            ulonglong2 kk = *(const ulonglong2*)(kv_s + d * 256 + sbase);  // 4 consec s
            float4 qa = *(const float4*)(q_s + d * 32 + r0);               // uniform bcast
            float4 qb = *(const float4*)(q_s + d * 32 + r0 + 4);
            u64 q0 = dup2(qa.x), q1 = dup2(qa.y), q2 = dup2(qa.z), q3 = dup2(qa.w);
            u64 q4 = dup2(qb.x), q5 = dup2(qb.y), q6 = dup2(qb.z), q7 = dup2(qb.w);
            fma2(acc[0][0], q0, kk.x); fma2(acc[0][1], q0, kk.y);
            fma2(acc[1][0], q1, kk.x); fma2(acc[1][1], q1, kk.y);
            fma2(acc[2][0], q2, kk.x); fma2(acc[2][1], q2, kk.y);
            fma2(acc[3][0], q3, kk.x); fma2(acc[3][1], q3, kk.y);
            fma2(acc[4][0], q4, kk.x); fma2(acc[4][1], q4, kk.y);
            fma2(acc[5][0], q5, kk.x); fma2(acc[5][1], q5, kk.y);
            fma2(acc[6][0], q6, kk.x); fma2(acc[6][1], q6, kk.y);
            fma2(acc[7][0], q7, kk.x); fma2(acc[7][1], q7, kk.y);
        }
        __syncthreads();             // kv_s free of readers

        if (c < 3) {                 // stage next K chunk; flies under the epilogue
            #pragma unroll
            for (int j = 0; j < 16; j++) {
                int idx = j * 1024 + tid * 4;
                int d = idx >> 8, s = idx & 255;
                cp16(kv_sh + idx * 4, kp + d * 1024 + (c + 1) * 256 + s);
            }
            cp_commit();
        }

        // epilogue: fully vectorized (float4 prev regs, float4 score stores)
        #pragma unroll
        for (int i = 0; i < 8; i++) {
            float2 a = unpk(acc[i][0]);
            float2 b = unpk(acc[i][1]);
            float4 pv = pf[i];
            float4 sv;
            sv.x = fmaf(a.x, scale, pv.x);
            sv.y = fmaf(a.y, scale, pv.y);
            sv.z = fmaf(b.x, scale, pv.z);
            sv.w = fmaf(b.y, scale, pv.w);
            *(float4*)(sp + (r0 + i) * 1024 + c * 256 + sbase) = sv;
            lsum[i] += (__expf(sv.x) + __expf(sv.y)) + (__expf(sv.z) + __expf(sv.w));
        }
    }

    // ---- row-sum reduce ----
    #pragma unroll
    for (int i = 0; i < 8; i++) {
        float s = lsum[i];
        #pragma unroll
        for (int off = 16; off; off >>= 1)
            s += __shfl_xor_sync(0xffffffffu, s, off);
        if (tx == 0) rsum_p[sgA * 32 + r0 + i] = s;
    }
    __syncthreads();
    if (tid < 32) rinv[tid] = 1.0f / (rsum_p[tid] + rsum_p[32 + tid]);
    __syncthreads();    // all sp STGs visible before cp.async re-reads

    // =============== Pass B: weights + output GEMM, 128-s chunks, dbl-buffered ===============
    const u32 st_sh = (u32)__cvta_generic_to_shared(stage);

    // stage chunk 0 -> buf 0
    #pragma unroll
    for (int j = 0; j < 4; j++) {
        int idx = j * 1024 + tid * 4;
        int row = idx >> 7, scol = idx & 127;
        cp16(st_sh + idx * 4,          sp + row * 1024 + scol);
        cp16(st_sh + (4096 + idx) * 4, mp + row * 1024 + scol);
    }
    cp_commit();

    const int sub = w >> 1, dh = w & 1;          // 4 s-subgroups (32 s) x 2 d-halves
    const int txg = tx & 3, tyg = tx >> 2;
    const int dcol = dh * 32 + txg * 8;
    const int rr = tid >> 3, t8 = tid & 7;       // conversion map: 8 threads per row
    const float ivr = rinv[rr];

    u64 oacc[4][4];
    #pragma unroll
    for (int i = 0; i < 4; i++)
        #pragma unroll
        for (int p = 0; p < 4; p++) oacc[i][p] = 0ull;

    for (int c = 0; c < 8; c++) {
        const int b = c & 1;
        const float* sb_s = stage + b * 8192;
        const float* mb_s = sb_s + 4096;

        cp_wait0();
        __syncthreads();             // buf b staged; w_s free; buf b^1 free

        if (c < 7) {                 // stage next chunk immediately (max overlap)
            #pragma unroll
            for (int j = 0; j < 4; j++) {
                int idx = j * 1024 + tid * 4;
                int row = idx >> 7, scol = idx & 127;
                cp16(st_sh + ((b ^ 1) * 8192 + idx) * 4,        sp + row * 1024 + (c + 1) * 128 + scol);
                cp16(st_sh + ((b ^ 1) * 8192 + 4096 + idx) * 4, mp + row * 1024 + (c + 1) * 128 + scol);
            }
            cp_commit();
        }

        // conversion: w = exp(score)*inv*mask -> gmem wts + smem w_s   (LDS-fed)
        #pragma unroll
        for (int j = 0; j < 4; j++) {
            int sl = t8 * 4 + j * 32;
            float4 sv = *(const float4*)(sb_s + rr * 128 + sl);
            float4 mv = *(const float4*)(mb_s + rr * 128 + sl);
            float4 w4;
            w4.x = __expf(sv.x) * ivr * mv.x;
            w4.y = __expf(sv.y) * ivr * mv.y;
            w4.z = __expf(sv.z) * ivr * mv.z;
            w4.w = __expf(sv.w) * ivr * mv.w;
            *(float4*)(wp + rr * 1024 + c * 128 + sl) = w4;
            *(float4*)(w_s + rr * WS + sl)            = w4;
        }
        __syncthreads();             // w_s ready

        const int sb = sub * 32;
        const float* vbase = vp + ((size_t)(c * 128 + sb)) * 64 + dcol;

        #pragma unroll 2
        for (int ss = 0; ss < 32; ss += 4) {
            float4 wv0 = *(const float4*)(w_s + (tyg +  0) * WS + sb + ss);
            float4 wv1 = *(const float4*)(w_s + (tyg +  8) * WS + sb + ss);
            float4 wv2 = *(const float4*)(w_s + (tyg + 16) * WS + sb + ss);
            float4 wv3 = *(const float4*)(w_s + (tyg + 24) * WS + sb + ss);
            ulonglong2 va[4], vb[4];
            #pragma unroll
            for (int u = 0; u < 4; u++) {
                va[u] = *(const ulonglong2*)(vbase + (ss + u) * 64);
                vb[u] = *(const ulonglong2*)(vbase + (ss + u) * 64 + 4);
            }
            #pragma unroll
            for (int u = 0; u < 4; u++) {
                u64 w0 = dup2(VSEL(wv0, u));
                u64 w1 = dup2(VSEL(wv1, u));
                u64 w2 = dup2(VSEL(wv2, u));
                u64 w3 = dup2(VSEL(wv3, u));
                fma2(oacc[0][0], w0, va[u].x); fma2(oacc[0][1], w0, va[u].y);
                fma2(oacc[0][2], w0, vb[u].x); fma2(oacc[0][3], w0, vb[u].y);
                fma2(oacc[1][0], w1, va[u].x); fma2(oacc[1][1], w1, va[u].y);
                fma2(oacc[1][2], w1, vb[u].x); fma2(oacc[1][3], w1, vb[u].y);
                fma2(oacc[2][0], w2, va[u].x); fma2(oacc[2][1], w2, va[u].y);
                fma2(oacc[2][2], w2, vb[u].x); fma2(oacc[2][3], w2, vb[u].y);
                fma2(oacc[3][0], w3, va[u].x); fma2(oacc[3][1], w3, va[u].y);
                fma2(oacc[3][2], w3, vb[u].x); fma2(oacc[3][3], w3, vb[u].y);
            }
        }
    }

    // ---- combine the 4 s-subgroup partials (stage bufs dead -> scratch in kv_s) ----
    __syncthreads();
    if (sub > 0) {
        #pragma unroll
        for (int i = 0; i < 4; i++) {
            float2 p0 = unpk(oacc[i][0]), p1 = unpk(oacc[i][1]);
            float2 p2 = unpk(oacc[i][2]), p3 = unpk(oacc[i][3]);
            float* bptr = scratch + (sub - 1) * 2176 + (tyg + 8 * i) * 68 + dcol;
            *(float4*)(bptr)     = make_float4(p0.x, p0.y, p1.x, p1.y);
            *(float4*)(bptr + 4) = make_float4(p2.x, p2.y, p3.x, p3.y);
        }
    }
    __syncthreads();
    if (sub == 0) {
        #pragma unroll
        for (int i = 0; i < 4; i++) {
            int row = tyg + 8 * i;
            float2 p0 = unpk(oacc[i][0]), p1 = unpk(oacc[i][1]);
            float2 p2 = unpk(oacc[i][2]), p3 = unpk(oacc[i][3]);
            float4 lo = make_float4(p0.x, p0.y, p1.x, p1.y);
            float4 hi = make_float4(p2.x, p2.y, p3.x, p3.y);
            #pragma unroll
            for (int s2 = 0; s2 < 3; s2++) {
                const float* bptr = scratch + s2 * 2176 + row * 68 + dcol;
                float4 a  = *(const float4*)(bptr);
                float4 b2 = *(const float4*)(bptr + 4);
                lo.x += a.x;  lo.y += a.y;  lo.z += a.z;  lo.w += a.w;
                hi.x += b2.x; hi.y += b2.y; hi.z += b2.z; hi.w += b2.w;
            }
            *(float4*)(op + row * 64 + dcol)     = lo;
            *(float4*)(op + row * 64 + dcol + 4) = hi;
        }
    }
}

extern "C" void kernel_launch(void* const* d_in, const int* in_sizes, int n_in,
                              void* d_out, int out_size) {
    const float* q     = (const float*)d_in[0];
    const float* k     = (const float*)d_in[1];
    const float* v     = (const float*)d_in[2];
    const float* prev  = (const float*)d_in[3];
    const float* mask  = (const float*)d_in[4];
    const float* scale = (const float*)d_in[5];

    float* out = (float*)d_out;                               // (4,16,1024,64)
    float* wts = out + (size_t)4 * 16 * 1024 * 64;            // (4,16,1024,1024)
    float* scr = wts + (size_t)4 * 16 * 1024 * 1024;          // (4,16,1024,1024)

    cudaFuncSetAttribute(attn_fused5_kernel,
                         cudaFuncAttributeMaxDynamicSharedMemorySize, SMEM_BYTES);

    attn_fused5_kernel<<<2048, 256, SMEM_BYTES>>>(q, k, v, prev, mask, scale,
                                                  out, wts, scr);
    (void)in_sizes; (void)n_in; (void)out_size;
}